// round 1
// baseline (speedup 1.0000x reference)
#include <cuda_runtime.h>
#include <cuda_bf16.h>

// Problem constants
#define BB 32
#define CC 256
#define HH 32
#define WW 32
#define HW 1024            // H*W
#define NROWS 32768        // B*H*W
#define KCODES 2048
#define DEPTH 4

// GEMM tile config
#define MT 64
#define NT 128
#define CT 32

// ---------------- scratch (device globals; no allocations) ----------------
__device__ float g_res[(size_t)NROWS * CC];    // residual, row-major [r][c]
__device__ float g_csum[(size_t)NROWS * CC];   // running sum of q
__device__ float g_znorm[NROWS];
__device__ float g_enorm[KCODES];
__device__ unsigned long long g_best[NROWS];
__device__ int g_counts[KCODES];

// ---------------- kernels ----------------

// z [B][C][HW] -> g_res[r][c] (r = b*HW + hw), and zero g_csum
__global__ void k_init_transpose(const float* __restrict__ z) {
    __shared__ float T[32][33];
    int b = blockIdx.z;
    int hw0 = blockIdx.y * 32;
    int c0 = blockIdx.x * 32;
    int tx = threadIdx.x & 31;
    int ty0 = threadIdx.x >> 5;        // 0..7
#pragma unroll
    for (int p = 0; p < 4; p++) {
        int cl = ty0 + p * 8;
        T[cl][tx] = z[((size_t)(b * CC + c0 + cl)) * HW + hw0 + tx];
    }
    __syncthreads();
#pragma unroll
    for (int p = 0; p < 4; p++) {
        int hwl = ty0 + p * 8;
        size_t a = (size_t)(b * HW + hw0 + hwl) * CC + c0 + tx;
        g_res[a] = T[tx][hwl];
        g_csum[a] = 0.0f;
    }
}

// per-row sum of squares of g_res -> g_znorm  (warp per row, deterministic)
__global__ void k_znorm() {
    int row = blockIdx.x * 8 + (threadIdx.x >> 5);
    int lane = threadIdx.x & 31;
    const float4* p = (const float4*)&g_res[(size_t)row * CC + lane * 8];
    float4 v0 = p[0], v1 = p[1];
    float s = v0.x * v0.x + v0.y * v0.y + v0.z * v0.z + v0.w * v0.w
            + v1.x * v1.x + v1.y * v1.y + v1.z * v1.z + v1.w * v1.w;
#pragma unroll
    for (int m = 16; m >= 1; m >>= 1) s += __shfl_xor_sync(0xffffffffu, s, m);
    if (lane == 0) g_znorm[row] = s;
}

// per-code sum of squares -> g_enorm
__global__ void k_enorm(const float* __restrict__ cb) {
    int row = blockIdx.x * 8 + (threadIdx.x >> 5);
    int lane = threadIdx.x & 31;
    const float4* p = (const float4*)&cb[(size_t)row * CC + lane * 8];
    float4 v0 = p[0], v1 = p[1];
    float s = v0.x * v0.x + v0.y * v0.y + v0.z * v0.z + v0.w * v0.w
            + v1.x * v1.x + v1.y * v1.y + v1.z * v1.z + v1.w * v1.w;
#pragma unroll
    for (int m = 16; m >= 1; m >>= 1) s += __shfl_xor_sync(0xffffffffu, s, m);
    if (lane == 0) g_enorm[row] = s;
}

__global__ void k_reset(int zero_counts) {
    int i = blockIdx.x * blockDim.x + threadIdx.x;
    if (i < NROWS) g_best[i] = 0xFFFFFFFFFFFFFFFFull;
    if (zero_counts && i < KCODES) g_counts[i] = 0;
}

// Fused distance GEMM + argmin.
// block: 256 threads, tile MT x NT, thread tile 4x8.
__global__ void __launch_bounds__(256)
k_gemm_argmin(const float* __restrict__ cb) {
    __shared__ float As[CT][MT + 4];   // +4 keeps float4 alignment
    __shared__ float Bs[CT][NT + 4];
    int tid = threadIdx.x;
    int tx = tid & 15;                  // 0..15 -> 8 cols each
    int ty = tid >> 4;                  // 0..15 -> 4 rows each
    int row0 = blockIdx.y * MT;
    int n0 = blockIdx.x * NT;

    float acc[4][8];
#pragma unroll
    for (int i = 0; i < 4; i++)
#pragma unroll
        for (int j = 0; j < 8; j++) acc[i][j] = 0.0f;

    const int ra = tid >> 2;            // 0..63  A row
    const int ca = (tid & 3) * 8;       // A col base
    const int nb = tid >> 1;            // 0..127 B row
    const int cbb = (tid & 1) * 16;     // B col base

    for (int kc = 0; kc < CC; kc += CT) {
        {   // load A chunk (64 x 32), store transposed
            const float* src = &g_res[(size_t)(row0 + ra) * CC + kc + ca];
            float4 v0 = *(const float4*)(src);
            float4 v1 = *(const float4*)(src + 4);
            As[ca + 0][ra] = v0.x; As[ca + 1][ra] = v0.y;
            As[ca + 2][ra] = v0.z; As[ca + 3][ra] = v0.w;
            As[ca + 4][ra] = v1.x; As[ca + 5][ra] = v1.y;
            As[ca + 6][ra] = v1.z; As[ca + 7][ra] = v1.w;
        }
        {   // load B chunk (128 x 32), store transposed
            const float* src = &cb[(size_t)(n0 + nb) * CC + kc + cbb];
#pragma unroll
            for (int j = 0; j < 4; j++) {
                float4 v = *(const float4*)(src + j * 4);
                Bs[cbb + j * 4 + 0][nb] = v.x;
                Bs[cbb + j * 4 + 1][nb] = v.y;
                Bs[cbb + j * 4 + 2][nb] = v.z;
                Bs[cbb + j * 4 + 3][nb] = v.w;
            }
        }
        __syncthreads();
#pragma unroll
        for (int c = 0; c < CT; c++) {
            float4 av = *(const float4*)&As[c][ty * 4];
            float4 bv0 = *(const float4*)&Bs[c][tx * 8];
            float4 bv1 = *(const float4*)&Bs[c][tx * 8 + 4];
            float a[4] = {av.x, av.y, av.z, av.w};
            float bvv[8] = {bv0.x, bv0.y, bv0.z, bv0.w, bv1.x, bv1.y, bv1.z, bv1.w};
#pragma unroll
            for (int i = 0; i < 4; i++)
#pragma unroll
                for (int j = 0; j < 8; j++) acc[i][j] = fmaf(a[i], bvv[j], acc[i][j]);
        }
        __syncthreads();
    }

    // epilogue: dist = (zn + en) - 2*acc  (matches reference fp32 rounding: 2*acc exact)
    float zn[4], en[8];
#pragma unroll
    for (int i = 0; i < 4; i++) zn[i] = g_znorm[row0 + ty * 4 + i];
#pragma unroll
    for (int j = 0; j < 8; j++) en[j] = g_enorm[n0 + tx * 8 + j];

#pragma unroll
    for (int i = 0; i < 4; i++) {
        unsigned long long best = 0xFFFFFFFFFFFFFFFFull;
#pragma unroll
        for (int j = 0; j < 8; j++) {
            float t = zn[i] + en[j];
            float dist = t - 2.0f * acc[i][j];
            unsigned long long key =
                ((unsigned long long)__float_as_uint(dist) << 32) |
                (unsigned int)(n0 + tx * 8 + j);
            best = min(best, key);
        }
#pragma unroll
        for (int m = 8; m >= 1; m >>= 1) {
            unsigned long long o = __shfl_xor_sync(0xffffffffu, best, m);
            best = min(best, o);
        }
        if (tx == 0) atomicMin(&g_best[row0 + ty * 4 + i], best);
    }
}

// gather codebook[idx], update residual/csum, write transposed outputs
__global__ void k_gather_update(const float* __restrict__ cb,
                                float* __restrict__ out_cum,
                                float* __restrict__ out_st,
                                float* __restrict__ out_idx,
                                int d) {
    __shared__ int idx_s[32];
    __shared__ float Tc[32][33];
    __shared__ float Tr[32][33];
    int b = blockIdx.z;
    int hw0 = blockIdx.y * 32;
    int c0 = blockIdx.x * 32;
    int tx = threadIdx.x & 31;
    int ty0 = threadIdx.x >> 5;

    if (threadIdx.x < 32) {
        int r = b * HW + hw0 + threadIdx.x;
        unsigned long long k = g_best[r];
        int idx = (int)(k & 0xFFFFFFFFull);
        idx_s[threadIdx.x] = idx;
        if (c0 == 0) {
            if (out_idx) out_idx[d * NROWS + r] = (float)idx;
            atomicAdd(&g_counts[idx], 1);
        }
    }
    __syncthreads();
#pragma unroll
    for (int p = 0; p < 4; p++) {
        int hwl = ty0 + p * 8;
        int r = b * HW + hw0 + hwl;
        int c = c0 + tx;
        float q = cb[(size_t)idx_s[hwl] * CC + c];
        size_t a = (size_t)r * CC + c;
        float res = g_res[a] - q;
        g_res[a] = res;
        float cs = g_csum[a] + q;
        g_csum[a] = cs;
        Tc[tx][hwl] = cs;   // [c][hw]
        Tr[tx][hwl] = res;
    }
    __syncthreads();
#pragma unroll
    for (int p = 0; p < 4; p++) {
        int cl = ty0 + p * 8;
        size_t o = ((size_t)(d * BB + b) * CC + c0 + cl) * HW + hw0 + tx;
        out_cum[o] = Tc[cl][tx];
        if (d == DEPTH - 1 && out_st) {
            out_st[((size_t)b * CC + c0 + cl) * HW + hw0 + tx] = Tr[cl][tx];
        }
    }
}

__global__ void k_perplexity(float* __restrict__ out_perp) {
    __shared__ float red[256];
    float s = 0.0f;
    const float inv = 1.0f / (float)(DEPTH * NROWS);
    for (int k = threadIdx.x; k < KCODES; k += 256) {
        float p = (float)g_counts[k] * inv;
        if (p > 0.0f) s += p * logf(p);   // clip(p,1e-10) irrelevant when p>0; p==0 term is 0
    }
    red[threadIdx.x] = s;
    __syncthreads();
    for (int m = 128; m >= 1; m >>= 1) {
        if (threadIdx.x < m) red[threadIdx.x] += red[threadIdx.x + m];
        __syncthreads();
    }
    if (threadIdx.x == 0) *out_perp = expf(-red[0]);
}

// ---------------- launch ----------------
extern "C" void kernel_launch(void* const* d_in, const int* in_sizes, int n_in,
                              void* d_out, int out_size) {
    const float* z = (const float*)d_in[0];
    const float* cb = (const float*)d_in[1];
    float* out = (float*)d_out;

    const long long SZ_CUM = (long long)DEPTH * BB * CC * HW;   // 33554432
    const long long SZ_ST = (long long)BB * CC * HW;            // 8388608
    const long long SZ_IDX = (long long)DEPTH * NROWS;          // 131072

    float* out_cum = out;
    float* out_st = (out_size >= SZ_CUM + SZ_ST) ? out + SZ_CUM : nullptr;
    float* out_idx = (out_size >= SZ_CUM + SZ_ST + SZ_IDX) ? out + SZ_CUM + SZ_ST : nullptr;
    float* out_perp = (out_size >= SZ_CUM + SZ_ST + SZ_IDX + 1)
                          ? out + SZ_CUM + SZ_ST + SZ_IDX : nullptr;

    dim3 tgrid(CC / 32, HW / 32, BB);          // 8 x 32 x 32
    k_init_transpose<<<tgrid, 256>>>(z);
    k_enorm<<<KCODES / 8, 256>>>(cb);

    for (int d = 0; d < DEPTH; d++) {
        k_znorm<<<NROWS / 8, 256>>>();
        k_reset<<<(NROWS + 255) / 256, 256>>>(d == 0 ? 1 : 0);
        k_gemm_argmin<<<dim3(KCODES / NT, NROWS / MT), 256>>>(cb);
        k_gather_update<<<tgrid, 256>>>(cb, out_cum, out_st, out_idx, d);
    }
    if (out_perp) k_perplexity<<<1, 256>>>(out_perp);
}